// round 4
// baseline (speedup 1.0000x reference)
#include <cuda_runtime.h>
#include <cstdint>

#define DINLINE __device__ __forceinline__

// ---------------- geometry ----------------
#define DTILE 64          // edges per tile
#define KDIM  256
#define HDIM  64

// ---------------- smem layout ----------------
#define OFF_W1F  0                       // 32kt x 8nt x 32 lanes x float2 = 65536
#define OFF_W2F  65536                   // 8kt x 8nt x 32 x float2 = 16384
#define OFF_HB   81920                   // h buffer: 64 rows x 64 floats = 16384
#define OFF_CMB  98304                   // 2 x (64 rows x 256 floats) = 131072
#define OFF_FLAG 229376                  // 4B is64 flag
#define SMEM_TOTAL 229392                // < 232448 (227KB opt-in max)

// ---------------- helpers ----------------
DINLINE uint32_t s2u(const void* p) {
    uint32_t a;
    asm("{ .reg .u64 t; cvta.to.shared.u64 t, %1; cvt.u32.u64 %0, t; }" : "=r"(a) : "l"(p));
    return a;
}

DINLINE float tf32r(float x) {   // round fp32 -> tf32 (rna), keep as fp32 bits
    uint32_t u;
    asm("cvt.rna.tf32.f32 %0, %1;" : "=r"(u) : "f"(x));
    return __uint_as_float(u);
}

DINLINE void cp16(uint32_t dst, const void* src) {
    asm volatile("cp.async.cg.shared.global [%0], [%1], 16;" :: "r"(dst), "l"(src));
}
DINLINE void cp_commit() { asm volatile("cp.async.commit_group;" ::: "memory"); }
DINLINE void cp_wait0()  { asm volatile("cp.async.wait_group 0;"  ::: "memory"); }

// D += A(m16k8,row) * B(k8n8,col), tf32 in / f32 out
DINLINE void mma8(float* c, uint32_t a0, uint32_t a1, uint32_t a2, uint32_t a3,
                  uint32_t b0, uint32_t b1) {
    asm volatile(
        "mma.sync.aligned.m16n8k8.row.col.f32.tf32.tf32.f32 "
        "{%0,%1,%2,%3}, {%4,%5,%6,%7}, {%8,%9}, {%0,%1,%2,%3};"
        : "+f"(c[0]), "+f"(c[1]), "+f"(c[2]), "+f"(c[3])
        : "r"(a0), "r"(a1), "r"(a2), "r"(a3), "r"(b0), "r"(b1));
}

// ---------------- comb tile issue (cp.async) ----------------
// comb[row][k] at byte: row*1024 + ((4q) ^ (4*(row&7)))*4 for float4 group q=k/4.
// Per-thread: q = tid&63 fixed, rows = it*4 + (tid>>6).
DINLINE void issue_tile(uint32_t dstbase, int be, int E, int q, int rb, int qq4,
                        const float* __restrict__ pbase, const float* __restrict__ u,
                        const void* __restrict__ bat, int is64) {
#pragma unroll
    for (int it = 0; it < 16; it++) {
        int row = it * 4 + rb;
        int e = be + row; e = (e < E) ? e : (E - 1);
        const float* p;
        if (q < 48) {
            p = pbase + (size_t)e * 64;
        } else {
            long b = is64 ? (long)((const long long*)bat)[e]
                          : (long)((const int*)bat)[e];
            p = u + b * 64 + qq4;
        }
        cp16(dstbase + (uint32_t)row * 1024u + (uint32_t)((q ^ (row & 7)) << 4), p);
    }
}

// ---------------- kernel ----------------
__global__ void __launch_bounds__(256, 1)
megnet_edge_kernel(const float* __restrict__ src, const float* __restrict__ dst,
                   const float* __restrict__ ea,  const float* __restrict__ u,
                   const int* __restrict__ bat,
                   const float* __restrict__ W1, const float* __restrict__ b1,
                   const float* __restrict__ W2, const float* __restrict__ b2,
                   float* __restrict__ out, int E, int NT) {
    extern __shared__ char smem[];
    const uint32_t sb = s2u(smem);
    const int tid = threadIdx.x;
    const int wid = tid >> 5;
    const int lane = tid & 31;

    // ---- one-time: pack W1/W2 into per-lane mma B-fragments (tf32-rounded) ----
    // slot s: lane = s&31, nt = (s>>5)&7, kt = s>>8;  b0=W[k][n], b1=W[k+4][n]
    for (int s = tid; s < 8192; s += 256) {
        int l = s & 31, nk = s >> 5, nt = nk & 7, kt = nk >> 3;
        int k = kt * 8 + (l & 3), n = nt * 8 + (l >> 2);
        float2 v = make_float2(tf32r(W1[k * 64 + n]), tf32r(W1[(k + 4) * 64 + n]));
        *(float2*)(smem + OFF_W1F + (size_t)s * 8) = v;
    }
    for (int s = tid; s < 2048; s += 256) {
        int l = s & 31, nk = s >> 5, nt = nk & 7, kt = nk >> 3;
        int k = kt * 8 + (l & 3), n = nt * 8 + (l >> 2);
        float2 v = make_float2(tf32r(W2[k * 64 + n]), tf32r(W2[(k + 4) * 64 + n]));
        *(float2*)(smem + OFF_W2F + (size_t)s * 8) = v;
    }
    if (tid == 0) {
        // batch dtype sniff: int64 payload (values < 2^31) has all-zero odd words
        int is64 = 1;
        for (int i = 1; i < 32; i += 2)
            if (bat[i] != 0) { is64 = 0; break; }
        *(int*)(smem + OFF_FLAG) = is64;
    }
    __syncthreads();
    const int is64 = *(const int*)(smem + OFF_FLAG);

    // ---- per-thread constants ----
    const int mtile = wid & 3;                 // 4 m-tiles of 16 rows
    const int nbase = (wid >> 2) * 4;          // n-half: nt = nbase..nbase+3
    const int r0 = mtile * 16 + (lane >> 2);   // my fragment row (and r0+8)
    const uint32_t swr = (uint32_t)(lane >> 2) << 2;   // (r0&7)<<2

    float2 rb1[4], rb2[4];
#pragma unroll
    for (int j = 0; j < 4; j++) {
        int col = (nbase + j) * 8 + 2 * (lane & 3);
        rb1[j] = make_float2(b1[col], b1[col + 1]);
        rb2[j] = make_float2(b2[col], b2[col + 1]);
    }

    // loader constants
    const int q = tid & 63, rb = tid >> 6;
    const int qq4 = (q & 15) * 4;
    const float* pbase = src + qq4;            // q<16
    if (q >= 16 && q < 32) pbase = dst + qq4;
    else if (q >= 32 && q < 48) pbase = ea + qq4;

    const int stride = gridDim.x;
    int t = blockIdx.x;
    int bi = 0;

    issue_tile(sb + OFF_CMB, t * DTILE, E, q, rb, qq4, pbase, u, bat, is64);
    cp_commit();

    for (; t < NT; t += stride) {
        cp_wait0();
        __syncthreads();                       // buf[bi] fully landed for all warps

        int nxt = t + stride;
        if (nxt < NT)
            issue_tile(sb + OFF_CMB + (bi ^ 1) * 65536, nxt * DTILE, E,
                       q, rb, qq4, pbase, u, bat, is64);
        cp_commit();

        // ---------- layer 1: C[16, 32] = comb[16,256] @ W1[:, nhalf] ----------
        const char* buf = smem + OFF_CMB + bi * 65536;
        const char* rowA0 = buf + r0 * 1024;
        const char* wf1 = smem + OFF_W1F + (size_t)(nbase * 32 + lane) * 8;
        float C[16];
#pragma unroll
        for (int i = 0; i < 16; i++) C[i] = 0.f;

#pragma unroll 4
        for (int kt = 0; kt < 32; kt++) {
            uint32_t c0 = (uint32_t)(kt * 8 + (lane & 3));
            uint32_t o0 = (c0 ^ swr) << 2;
            uint32_t o2 = o0 ^ 16;
            uint32_t a0 = *(const uint32_t*)(rowA0 + o0);
            uint32_t a1 = *(const uint32_t*)(rowA0 + 8192 + o0);
            uint32_t a2 = *(const uint32_t*)(rowA0 + o2);
            uint32_t a3 = *(const uint32_t*)(rowA0 + 8192 + o2);
            const float2* wf = (const float2*)(wf1 + (size_t)kt * 8 * 32 * 8);
#pragma unroll
            for (int j = 0; j < 4; j++) {
                float2 b = wf[j * 32];
                mma8(C + j * 4, a0, a1, a2, a3,
                     __float_as_uint(b.x), __float_as_uint(b.y));
            }
        }

        // ---------- h = relu(C + b1) -> smem (tf32-rounded) ----------
        char* hrow0 = smem + OFF_HB + r0 * 256;
#pragma unroll
        for (int j = 0; j < 4; j++) {
            uint32_t col = (uint32_t)((nbase + j) * 8 + 2 * (lane & 3));
            uint32_t ho = (col ^ swr) << 2;
            float2 v0 = make_float2(tf32r(fmaxf(C[j * 4 + 0] + rb1[j].x, 0.f)),
                                    tf32r(fmaxf(C[j * 4 + 1] + rb1[j].y, 0.f)));
            float2 v1 = make_float2(tf32r(fmaxf(C[j * 4 + 2] + rb1[j].x, 0.f)),
                                    tf32r(fmaxf(C[j * 4 + 3] + rb1[j].y, 0.f)));
            *(float2*)(hrow0 + ho) = v0;
            *(float2*)(hrow0 + 8 * 256 + ho) = v1;
        }
        __syncthreads();                       // hbuf visible to n-half partner warps

        // ---------- layer 2: C2[16, 32] = h[16,64] @ W2[:, nhalf] ----------
        float C2[16];
#pragma unroll
        for (int i = 0; i < 16; i++) C2[i] = 0.f;
        const char* wf2 = smem + OFF_W2F + (size_t)(nbase * 32 + lane) * 8;
#pragma unroll
        for (int kt = 0; kt < 8; kt++) {
            uint32_t c0 = (uint32_t)(kt * 8 + (lane & 3));
            uint32_t o0 = (c0 ^ swr) << 2;
            uint32_t o2 = o0 ^ 16;
            uint32_t a0 = *(const uint32_t*)(hrow0 + o0);
            uint32_t a1 = *(const uint32_t*)(hrow0 + 2048 + o0);
            uint32_t a2 = *(const uint32_t*)(hrow0 + o2);
            uint32_t a3 = *(const uint32_t*)(hrow0 + 2048 + o2);
            const float2* wf = (const float2*)(wf2 + (size_t)kt * 8 * 32 * 8);
#pragma unroll
            for (int j = 0; j < 4; j++) {
                float2 b = wf[j * 32];
                mma8(C2 + j * 4, a0, a1, a2, a3,
                     __float_as_uint(b.x), __float_as_uint(b.y));
            }
        }

        // ---------- out = relu(C2 + b2) -> gmem ----------
        long e0 = (long)t * DTILE + r0;
#pragma unroll
        for (int j = 0; j < 4; j++) {
            int col = (nbase + j) * 8 + 2 * (lane & 3);
            if (e0 < E) {
                float2 v = make_float2(fmaxf(C2[j * 4 + 0] + rb2[j].x, 0.f),
                                       fmaxf(C2[j * 4 + 1] + rb2[j].y, 0.f));
                *(float2*)(out + e0 * 64 + col) = v;
            }
            if (e0 + 8 < E) {
                float2 v = make_float2(fmaxf(C2[j * 4 + 2] + rb2[j].x, 0.f),
                                       fmaxf(C2[j * 4 + 3] + rb2[j].y, 0.f));
                *(float2*)(out + (e0 + 8) * 64 + col) = v;
            }
        }
        __syncthreads();   // comb[bi] & hbuf free for reuse before next issue/compute
        bi ^= 1;
    }
}

// ---------------- launch ----------------
extern "C" void kernel_launch(void* const* d_in, const int* in_sizes, int n_in,
                              void* d_out, int out_size) {
    const float* src = (const float*)d_in[0];
    const float* dst = (const float*)d_in[1];
    const float* ea  = (const float*)d_in[2];
    const float* u   = (const float*)d_in[3];
    const int*   bat = (const int*)d_in[4];   // int32 or int64 payload; sniffed in-kernel
    const float* W1  = (const float*)d_in[5];
    const float* b1  = (const float*)d_in[6];
    const float* W2  = (const float*)d_in[7];
    const float* b2  = (const float*)d_in[8];
    float* out = (float*)d_out;

    int E  = in_sizes[0] / 64;
    int NT = (E + DTILE - 1) / DTILE;

    int dev = 0;
    cudaGetDevice(&dev);
    int nsm = 148;
    cudaDeviceGetAttribute(&nsm, cudaDevAttrMultiProcessorCount, dev);
    int grid = (NT < nsm) ? NT : nsm;

    cudaFuncSetAttribute(megnet_edge_kernel,
                         cudaFuncAttributeMaxDynamicSharedMemorySize, SMEM_TOTAL);
    megnet_edge_kernel<<<grid, 256, SMEM_TOTAL>>>(src, dst, ea, u, bat,
                                                  W1, b1, W2, b2, out, E, NT);
    (void)n_in; (void)out_size;
}

// round 5
// speedup vs baseline: 2.2264x; 2.2264x over previous
#include <cuda_runtime.h>
#include <cstdint>

#define DINLINE __device__ __forceinline__

// ---------------- geometry ----------------
#define DTILE 256         // edges per tile (8 warps x 32 rows)
#define KDIM  256
#define HDIM  64

// ---------------- smem layout ----------------
#define OFF_W1F  0                       // 32kt x 8nt x 32 lanes x float2 = 65536
#define OFF_W2F  65536                   // 8kt x 8nt x 32 x float2 = 16384
#define OFF_HB   81920                   // 8 warps x (32 rows x 64 cols x 4B) = 65536
#define OFF_CMB  147456                  // 8 warps x 2 slots x 4KB = 65536
#define OFF_FLAG 212992                  // 4B is64 flag
#define OFF_B1   213056                  // 256B
#define OFF_B2   213312                  // 256B
#define SMEM_TOTAL 213568                // < 232448

// ---------------- helpers ----------------
DINLINE float tf32r(float x) {   // round fp32 -> tf32 (rna), keep as fp32 bits
    uint32_t u;
    asm("cvt.rna.tf32.f32 %0, %1;" : "=r"(u) : "f"(x));
    return __uint_as_float(u);
}

DINLINE uint32_t s2u(const void* p) {
    uint32_t a;
    asm("{ .reg .u64 t; cvta.to.shared.u64 t, %1; cvt.u32.u64 %0, t; }" : "=r"(a) : "l"(p));
    return a;
}

DINLINE void cp16(uint32_t dst, const void* src) {
    asm volatile("cp.async.cg.shared.global [%0], [%1], 16;" :: "r"(dst), "l"(src));
}
DINLINE void cp_commit() { asm volatile("cp.async.commit_group;" ::: "memory"); }
DINLINE void cp_wait1()  { asm volatile("cp.async.wait_group 1;"  ::: "memory"); }
DINLINE void cp_wait0()  { asm volatile("cp.async.wait_group 0;"  ::: "memory"); }

// D += A(m16k8,row) * B(k8n8,col), tf32 in / f32 out
DINLINE void mma8(float* c, uint32_t a0, uint32_t a1, uint32_t a2, uint32_t a3,
                  uint32_t b0, uint32_t b1) {
    asm volatile(
        "mma.sync.aligned.m16n8k8.row.col.f32.tf32.tf32.f32 "
        "{%0,%1,%2,%3}, {%4,%5,%6,%7}, {%8,%9}, {%0,%1,%2,%3};"
        : "+f"(c[0]), "+f"(c[1]), "+f"(c[2]), "+f"(c[3])
        : "r"(a0), "r"(a1), "r"(a2), "r"(a3), "r"(b0), "r"(b1));
}

// ---------------- per-warp chunk issue ----------------
// chunk = 32 rows x 32 cols (4KB), rows = this warp's rows, cols [c*32, c*32+32)
// c: 0,1 src | 2,3 dest | 4,5 edge_attr | 6,7 u[batch]
// smem chunk layout: row stride 128B, float4-quad q stored at q ^ (row&7)
DINLINE void issue_chunk(uint32_t dstbase, long ebase, int E, int c,
                         const float* __restrict__ s0, const float* __restrict__ s1,
                         const float* __restrict__ s2, const float* __restrict__ u,
                         const void* __restrict__ bat, int is64, int lane) {
    const int coff = (c & 1) * 32;
#pragma unroll
    for (int i = 0; i < 8; i++) {
        int flat = i * 32 + lane;
        int row = flat >> 3, q = flat & 7;
        long e = ebase + row; if (e >= E) e = E - 1;
        const float* p;
        if (c < 6) {
            const float* base = (c < 2) ? s0 : ((c < 4) ? s1 : s2);
            p = base + e * 64 + coff + q * 4;
        } else {
            long b = is64 ? (long)((const long long*)bat)[e]
                          : (long)((const int*)bat)[e];
            p = u + b * 64 + coff + q * 4;
        }
        cp16(dstbase + (uint32_t)(row * 128) + (uint32_t)((q ^ (row & 7)) << 4), p);
    }
}

// ---------------- kernel ----------------
__global__ void __launch_bounds__(256, 1)
megnet_edge_kernel(const float* __restrict__ src, const float* __restrict__ dst,
                   const float* __restrict__ ea,  const float* __restrict__ u,
                   const int* __restrict__ bat,
                   const float* __restrict__ W1, const float* __restrict__ b1,
                   const float* __restrict__ W2, const float* __restrict__ b2,
                   float* __restrict__ out, int E, int NT) {
    extern __shared__ char smem[];
    const uint32_t sb = s2u(smem);
    const int tid = threadIdx.x;
    const int w = tid >> 5;
    const int lane = tid & 31;

    // ---- one-time: pack W1/W2 into per-lane mma B-fragments (tf32 rna) ----
    // slot s: lane = s&31, nt = (s>>5)&7, kt = s>>8;  b0=W[k][n], b1=W[k+4][n]
    for (int s = tid; s < 8192; s += 256) {
        int l = s & 31, nk = s >> 5, nt = nk & 7, kt = nk >> 3;
        int k = kt * 8 + (l & 3), n = nt * 8 + (l >> 2);
        float2 v = make_float2(tf32r(W1[k * 64 + n]), tf32r(W1[(k + 4) * 64 + n]));
        *(float2*)(smem + OFF_W1F + (size_t)s * 8) = v;
    }
    for (int s = tid; s < 2048; s += 256) {
        int l = s & 31, nk = s >> 5, nt = nk & 7, kt = nk >> 3;
        int k = kt * 8 + (l & 3), n = nt * 8 + (l >> 2);
        float2 v = make_float2(tf32r(W2[k * 64 + n]), tf32r(W2[(k + 4) * 64 + n]));
        *(float2*)(smem + OFF_W2F + (size_t)s * 8) = v;
    }
    if (tid < 64) {
        ((float*)(smem + OFF_B1))[tid] = b1[tid];
        ((float*)(smem + OFF_B2))[tid] = b2[tid];
    }
    if (tid == 0) {
        // batch dtype sniff: int64 payload (values < 2^31) has all-zero odd words
        int is64 = 1;
        for (int i = 1; i < 32; i += 2)
            if (bat[i] != 0) { is64 = 0; break; }
        *(int*)(smem + OFF_FLAG) = is64;
    }
    __syncthreads();
    const int is64 = *(const int*)(smem + OFF_FLAG);
    const float* b1s = (const float*)(smem + OFF_B1);
    const float* b2s = (const float*)(smem + OFF_B2);

    // ---- per-warp constants ----
    const int r0 = lane >> 2;                    // 0..7
    const int l3 = lane & 3;
    const uint32_t slot0 = sb + OFF_CMB + (uint32_t)w * 8192u;   // 2 slots x 4KB
    char* hbp = smem + OFF_HB + (size_t)w * 8192;                // 32 x 64 floats

    const int bid = blockIdx.x, grid = gridDim.x;
    const int numT = (NT - bid + grid - 1) / grid;               // tiles for this CTA
    const long total = (long)numT * 8;

    float C[64];                                 // [m-sub(2)][nt(8)][4]

    // prologue: chunk 0 of tile bid
    issue_chunk(slot0, (long)bid * DTILE + w * 32, E, 0,
                src, dst, ea, u, bat, is64, lane);
    cp_commit();

    for (long n = 0; n < total; n++) {
        const int c = (int)(n & 7);
        const long tile = bid + (n >> 3) * grid;

        __syncwarp();
        if (n + 1 < total) {
            long n1 = n + 1;
            long t1 = bid + (n1 >> 3) * grid;
            issue_chunk(slot0 + (uint32_t)((n1 & 1) * 4096),
                        t1 * DTILE + w * 32, E, (int)(n1 & 7),
                        src, dst, ea, u, bat, is64, lane);
            cp_commit();
            cp_wait1();          // chunk n landed
        } else {
            cp_wait0();
        }
        __syncwarp();

        if (c == 0) {
#pragma unroll
            for (int i = 0; i < 64; i++) C[i] = 0.f;
        }

        // ---------- layer-1 partial: 4 k-groups of this chunk ----------
        const char* cbp = smem + OFF_CMB + (size_t)w * 8192 + (size_t)(n & 1) * 4096;
        const char* A = cbp + r0 * 128 + l3 * 4;
#pragma unroll
        for (int kt = 0; kt < 4; kt++) {
            const int ktg = c * 4 + kt;
            const uint32_t x0 = (uint32_t)(((kt * 2) ^ r0) << 4);
            uint32_t a00 = *(const uint32_t*)(A + x0);
            uint32_t a01 = *(const uint32_t*)(A + 1024 + x0);
            uint32_t a02 = *(const uint32_t*)(A + (x0 ^ 16));
            uint32_t a03 = *(const uint32_t*)(A + 1024 + (x0 ^ 16));
            uint32_t a10 = *(const uint32_t*)(A + 2048 + x0);
            uint32_t a11 = *(const uint32_t*)(A + 3072 + x0);
            uint32_t a12 = *(const uint32_t*)(A + 2048 + (x0 ^ 16));
            uint32_t a13 = *(const uint32_t*)(A + 3072 + (x0 ^ 16));
            const char* wf = smem + OFF_W1F + (size_t)(ktg * 8) * 256 + (size_t)lane * 8;
#pragma unroll
            for (int nt = 0; nt < 8; nt++) {
                float2 b = *(const float2*)(wf + nt * 256);
                uint32_t b0 = __float_as_uint(b.x), b1r = __float_as_uint(b.y);
                mma8(C + nt * 4,      a00, a01, a02, a03, b0, b1r);
                mma8(C + 32 + nt * 4, a10, a11, a12, a13, b0, b1r);
            }
        }

        if (c != 7) continue;

        // ---------- h = relu(C + b1) -> per-warp smem (tf32 rna) ----------
#pragma unroll
        for (int m = 0; m < 2; m++) {
#pragma unroll
            for (int nt = 0; nt < 8; nt++) {
                const int col0 = nt * 8 + 2 * l3;
                float2 bb = *(const float2*)(b1s + col0);
                const float* Cm = C + m * 32 + nt * 4;
                const int q = col0 >> 2;
                char* base = hbp + (m * 16 + r0) * 256 + ((q ^ r0) << 4) + ((l3 & 1) * 8);
                float2 v0 = make_float2(tf32r(fmaxf(Cm[0] + bb.x, 0.f)),
                                        tf32r(fmaxf(Cm[1] + bb.y, 0.f)));
                float2 v1 = make_float2(tf32r(fmaxf(Cm[2] + bb.x, 0.f)),
                                        tf32r(fmaxf(Cm[3] + bb.y, 0.f)));
                *(float2*)(base) = v0;
                *(float2*)(base + 2048) = v1;
            }
        }
        __syncwarp();

        // ---------- layer 2: C = h[32,64] @ W2 ----------
#pragma unroll
        for (int i = 0; i < 64; i++) C[i] = 0.f;
        const char* Ah = hbp + r0 * 256 + l3 * 4;
#pragma unroll
        for (int kt = 0; kt < 8; kt++) {
            const uint32_t x0 = (uint32_t)(((kt * 2) ^ r0) << 4);
            uint32_t a00 = *(const uint32_t*)(Ah + x0);
            uint32_t a01 = *(const uint32_t*)(Ah + 2048 + x0);
            uint32_t a02 = *(const uint32_t*)(Ah + (x0 ^ 16));
            uint32_t a03 = *(const uint32_t*)(Ah + 2048 + (x0 ^ 16));
            uint32_t a10 = *(const uint32_t*)(Ah + 4096 + x0);
            uint32_t a11 = *(const uint32_t*)(Ah + 6144 + x0);
            uint32_t a12 = *(const uint32_t*)(Ah + 4096 + (x0 ^ 16));
            uint32_t a13 = *(const uint32_t*)(Ah + 6144 + (x0 ^ 16));
            const char* wf = smem + OFF_W2F + (size_t)(kt * 8) * 256 + (size_t)lane * 8;
#pragma unroll
            for (int nt = 0; nt < 8; nt++) {
                float2 b = *(const float2*)(wf + nt * 256);
                uint32_t b0 = __float_as_uint(b.x), b1r = __float_as_uint(b.y);
                mma8(C + nt * 4,      a00, a01, a02, a03, b0, b1r);
                mma8(C + 32 + nt * 4, a10, a11, a12, a13, b0, b1r);
            }
        }

        // ---------- out = relu(C + b2) -> gmem ----------
        const long e00 = tile * DTILE + w * 32 + r0;
#pragma unroll
        for (int m = 0; m < 2; m++) {
            const long e = e00 + m * 16;
#pragma unroll
            for (int nt = 0; nt < 8; nt++) {
                const int col0 = nt * 8 + 2 * l3;
                float2 bb = *(const float2*)(b2s + col0);
                const float* Cm = C + m * 32 + nt * 4;
                if (e < E) {
                    float2 v = make_float2(fmaxf(Cm[0] + bb.x, 0.f),
                                           fmaxf(Cm[1] + bb.y, 0.f));
                    *(float2*)(out + e * 64 + col0) = v;
                }
                if (e + 8 < E) {
                    float2 v = make_float2(fmaxf(Cm[2] + bb.x, 0.f),
                                           fmaxf(Cm[3] + bb.y, 0.f));
                    *(float2*)(out + (e + 8) * 64 + col0) = v;
                }
            }
        }
    }
}

// ---------------- launch ----------------
extern "C" void kernel_launch(void* const* d_in, const int* in_sizes, int n_in,
                              void* d_out, int out_size) {
    const float* src = (const float*)d_in[0];
    const float* dst = (const float*)d_in[1];
    const float* ea  = (const float*)d_in[2];
    const float* u   = (const float*)d_in[3];
    const int*   bat = (const int*)d_in[4];   // int32 or int64 payload; sniffed in-kernel
    const float* W1  = (const float*)d_in[5];
    const float* b1  = (const float*)d_in[6];
    const float* W2  = (const float*)d_in[7];
    const float* b2  = (const float*)d_in[8];
    float* out = (float*)d_out;

    int E  = in_sizes[0] / 64;
    int NT = (E + DTILE - 1) / DTILE;

    int dev = 0;
    cudaGetDevice(&dev);
    int nsm = 148;
    cudaDeviceGetAttribute(&nsm, cudaDevAttrMultiProcessorCount, dev);
    int grid = (NT < nsm) ? NT : nsm;

    cudaFuncSetAttribute(megnet_edge_kernel,
                         cudaFuncAttributeMaxDynamicSharedMemorySize, SMEM_TOTAL);
    megnet_edge_kernel<<<grid, 256, SMEM_TOTAL>>>(src, dst, ea, u, bat,
                                                  W1, b1, W2, b2, out, E, NT);
    (void)n_in; (void)out_size;
}